// round 2
// baseline (speedup 1.0000x reference)
#include <cuda_runtime.h>
#include <math.h>

#define T_TOK 4096
#define H_DIM 2048
#define I_DIM 2048
#define N_EXP 16
#define TOPK  2
#define MAXP  (T_TOK*TOPK)   // 8192 token-expert pairs (always exactly this many)

// ---------------- scratch (static device globals; no allocation) ----------------
__device__ int   g_sel [T_TOK*TOPK];   // selected expert ids per token
__device__ float g_selw[T_TOK*TOPK];   // normalized top-2 weights per token
__device__ int   g_cnt [N_EXP];        // tokens per expert
__device__ int   g_off [N_EXP+1];      // exclusive prefix offsets
__device__ int   g_tok [MAXP];         // expert-grouped token ids
__device__ float g_cw  [MAXP];         // expert-grouped coef weights
__device__ float g_gu  [(size_t)MAXP * 2 * I_DIM];  // gate_up buffer (128 MB)
__device__ float g_h   [(size_t)MAXP * I_DIM];      // silu(g)*u buffer (64 MB)

// ---------------- kernel 0: zero output + counters ----------------
__global__ void zero_kernel(float* __restrict__ out)
{
    int n = T_TOK * H_DIM;
    for (int i = blockIdx.x * blockDim.x + threadIdx.x; i < n;
         i += gridDim.x * blockDim.x)
        out[i] = 0.0f;
    if (blockIdx.x == 0 && threadIdx.x < N_EXP) g_cnt[threadIdx.x] = 0;
}

// ---------------- kernel 1: gating (logits -> top2 -> renormalized weights) ----
__global__ void gate_kernel(const float* __restrict__ x,
                            const float* __restrict__ gw)
{
    __shared__ float sx[H_DIM];
    __shared__ float slog[N_EXP];
    const int t = blockIdx.x;
    const float* xr = x + (size_t)t * H_DIM;
    for (int i = threadIdx.x; i < H_DIM; i += blockDim.x) sx[i] = xr[i];
    __syncthreads();

    const int warp = threadIdx.x >> 5, lane = threadIdx.x & 31;
    for (int e = warp; e < N_EXP; e += 4) {
        const float* g = gw + (size_t)e * H_DIM;
        float s = 0.0f;
        for (int h = lane; h < H_DIM; h += 32) s += sx[h] * g[h];
        #pragma unroll
        for (int o = 16; o; o >>= 1) s += __shfl_xor_sync(0xffffffff, s, o);
        if (lane == 0) slog[e] = s;
    }
    __syncthreads();

    if (threadIdx.x == 0) {
        // softmax is monotone: top-2 of logits == top-2 of scores.
        // renormalized top-2 weight = exp(v_i - v0) / (1 + exp(v1 - v0)).
        int i0 = 0; float v0 = slog[0];
        for (int e = 1; e < N_EXP; e++)
            if (slog[e] > v0) { v0 = slog[e]; i0 = e; }   // strict > keeps first (ties like jax)
        int i1 = -1; float v1 = -INFINITY;
        for (int e = 0; e < N_EXP; e++)
            if (e != i0 && slog[e] > v1) { v1 = slog[e]; i1 = e; }
        float e1 = expf(v1 - v0);
        float inv = 1.0f / (1.0f + e1);
        g_sel [t*2]   = i0;  g_selw[t*2]   = inv;
        g_sel [t*2+1] = i1;  g_selw[t*2+1] = e1 * inv;
        atomicAdd(&g_cnt[i0], 1);
        atomicAdd(&g_cnt[i1], 1);
    }
}

// ---------------- kernel 2: deterministic counting-sort grouping ---------------
__global__ void group_kernel()
{
    const int e = blockIdx.x;
    __shared__ int sbase;
    __shared__ int scan[256];

    if (threadIdx.x == 0) {
        int o = 0;
        for (int i = 0; i < e; i++) o += g_cnt[i];
        sbase = o;
        g_off[e] = o;
        if (e == N_EXP - 1) g_off[N_EXP] = o + g_cnt[e];
    }
    __syncthreads();
    int base = sbase;

    for (int t0 = 0; t0 < T_TOK; t0 += 256) {
        int t = t0 + threadIdx.x;
        int pred = 0; float w = 0.0f;
        int s0 = g_sel[t*2], s1 = g_sel[t*2+1];
        if      (s0 == e) { pred = 1; w = g_selw[t*2];   }
        else if (s1 == e) { pred = 1; w = g_selw[t*2+1]; }

        scan[threadIdx.x] = pred;
        __syncthreads();
        for (int o = 1; o < 256; o <<= 1) {            // Hillis-Steele inclusive scan
            int v = 0;
            if (threadIdx.x >= o) v = scan[threadIdx.x - o];
            __syncthreads();
            scan[threadIdx.x] += v;
            __syncthreads();
        }
        int excl = scan[threadIdx.x] - pred;
        if (pred) { g_tok[base + excl] = t; g_cw[base + excl] = w; }
        int total = scan[255];
        __syncthreads();
        base += total;
    }
}

// ---------------- SGEMM helpers ----------------
__device__ __forceinline__ float4 ld4(const float* p)
{ return *reinterpret_cast<const float4*>(p); }

// ---------------- kernel 3: GEMM1  gu[pair, 0:2I] = x[tok] . w13_e^T --------------
__global__ __launch_bounds__(256, 2)
void gemm1_kernel(const float* __restrict__ x, const float* __restrict__ ws)
{
    const int e   = blockIdx.z;
    const int off = g_off[e];
    const int cnt = g_off[e+1] - off;
    const int m0  = blockIdx.y * 128;
    if (m0 >= cnt) return;
    const int n0  = blockIdx.x * 128;

    __shared__ float As[16][128];
    __shared__ float Bs[16][128];

    const int tid  = threadIdx.x;
    const int tx   = tid & 15;
    const int ty   = tid >> 4;
    const int lrow = tid >> 1;           // 0..127
    const int lk   = (tid & 1) * 8;      // 0 or 8

    const int mr = m0 + lrow;
    const bool avalid = (mr < cnt);
    const float* aptr = avalid ? (x + (size_t)g_tok[off + mr] * H_DIM + lk) : x;
    const float* bptr = ws + (size_t)e * (2 * (size_t)I_DIM) * H_DIM
                           + (size_t)(n0 + lrow) * H_DIM + lk;

    float4 ra0, ra1, rb0, rb1;
    const float4 z4 = make_float4(0.f, 0.f, 0.f, 0.f);
    ra0 = avalid ? ld4(aptr)     : z4;
    ra1 = avalid ? ld4(aptr + 4) : z4;
    rb0 = ld4(bptr);
    rb1 = ld4(bptr + 4);

    float acc[8][8];
    #pragma unroll
    for (int i = 0; i < 8; i++)
        #pragma unroll
        for (int j = 0; j < 8; j++) acc[i][j] = 0.0f;

    for (int k0 = 0; k0 < H_DIM; k0 += 16) {
        As[lk+0][lrow] = ra0.x; As[lk+1][lrow] = ra0.y;
        As[lk+2][lrow] = ra0.z; As[lk+3][lrow] = ra0.w;
        As[lk+4][lrow] = ra1.x; As[lk+5][lrow] = ra1.y;
        As[lk+6][lrow] = ra1.z; As[lk+7][lrow] = ra1.w;
        Bs[lk+0][lrow] = rb0.x; Bs[lk+1][lrow] = rb0.y;
        Bs[lk+2][lrow] = rb0.z; Bs[lk+3][lrow] = rb0.w;
        Bs[lk+4][lrow] = rb1.x; Bs[lk+5][lrow] = rb1.y;
        Bs[lk+6][lrow] = rb1.z; Bs[lk+7][lrow] = rb1.w;
        __syncthreads();

        int kn = k0 + 16;
        if (kn < H_DIM) {                 // register prefetch of next k-tile
            ra0 = avalid ? ld4(aptr + kn)     : z4;
            ra1 = avalid ? ld4(aptr + kn + 4) : z4;
            rb0 = ld4(bptr + kn);
            rb1 = ld4(bptr + kn + 4);
        }

        #pragma unroll
        for (int k = 0; k < 16; k++) {
            float a[8], b[8];
            #pragma unroll
            for (int i = 0; i < 8; i++) a[i] = As[k][ty*8 + i];
            #pragma unroll
            for (int j = 0; j < 8; j++) b[j] = Bs[k][tx*8 + j];
            #pragma unroll
            for (int i = 0; i < 8; i++)
                #pragma unroll
                for (int j = 0; j < 8; j++) acc[i][j] += a[i] * b[j];
        }
        __syncthreads();
    }

    #pragma unroll
    for (int i = 0; i < 8; i++) {
        int m = m0 + ty*8 + i;
        if (m < cnt) {
            float* dst = g_gu + (size_t)(off + m) * (2*I_DIM) + n0 + tx*8;
            float4 v0 = make_float4(acc[i][0], acc[i][1], acc[i][2], acc[i][3]);
            float4 v1 = make_float4(acc[i][4], acc[i][5], acc[i][6], acc[i][7]);
            *reinterpret_cast<float4*>(dst)     = v0;
            *reinterpret_cast<float4*>(dst + 4) = v1;
        }
    }
}

// ---------------- kernel 4: h = silu(g) * u  ----------------
__global__ void silu_kernel()
{
    // MAXP rows * (I_DIM/4) float4 per row = 8192 * 512 = 4194304 threads
    int i = blockIdx.x * blockDim.x + threadIdx.x;
    int r  = i >> 9;          // /512
    int c4 = i & 511;
    const float* grow = g_gu + (size_t)r * (2*I_DIM) + c4*4;
    float4 g = ld4(grow);
    float4 u = ld4(grow + I_DIM);
    float4 h;
    h.x = g.x / (1.0f + expf(-g.x)) * u.x;
    h.y = g.y / (1.0f + expf(-g.y)) * u.y;
    h.z = g.z / (1.0f + expf(-g.z)) * u.z;
    h.w = g.w / (1.0f + expf(-g.w)) * u.w;
    *reinterpret_cast<float4*>(g_h + (size_t)r * I_DIM + c4*4) = h;
}

// ---------------- kernel 5: GEMM2  out[tok] += coef * (h . w2_e^T) ----------------
__global__ __launch_bounds__(256, 2)
void gemm2_kernel(float* __restrict__ out, const float* __restrict__ w2s)
{
    const int e   = blockIdx.z;
    const int off = g_off[e];
    const int cnt = g_off[e+1] - off;
    const int m0  = blockIdx.y * 128;
    if (m0 >= cnt) return;
    const int n0  = blockIdx.x * 128;

    __shared__ float As[16][128];
    __shared__ float Bs[16][128];

    const int tid  = threadIdx.x;
    const int tx   = tid & 15;
    const int ty   = tid >> 4;
    const int lrow = tid >> 1;
    const int lk   = (tid & 1) * 8;

    const int mr = m0 + lrow;
    const bool avalid = (mr < cnt);
    const float* aptr = avalid ? (g_h + (size_t)(off + mr) * I_DIM + lk) : g_h;
    const float* bptr = w2s + (size_t)e * H_DIM * I_DIM
                            + (size_t)(n0 + lrow) * I_DIM + lk;

    float4 ra0, ra1, rb0, rb1;
    const float4 z4 = make_float4(0.f, 0.f, 0.f, 0.f);
    ra0 = avalid ? ld4(aptr)     : z4;
    ra1 = avalid ? ld4(aptr + 4) : z4;
    rb0 = ld4(bptr);
    rb1 = ld4(bptr + 4);

    float acc[8][8];
    #pragma unroll
    for (int i = 0; i < 8; i++)
        #pragma unroll
        for (int j = 0; j < 8; j++) acc[i][j] = 0.0f;

    for (int k0 = 0; k0 < I_DIM; k0 += 16) {
        As[lk+0][lrow] = ra0.x; As[lk+1][lrow] = ra0.y;
        As[lk+2][lrow] = ra0.z; As[lk+3][lrow] = ra0.w;
        As[lk+4][lrow] = ra1.x; As[lk+5][lrow] = ra1.y;
        As[lk+6][lrow] = ra1.z; As[lk+7][lrow] = ra1.w;
        Bs[lk+0][lrow] = rb0.x; Bs[lk+1][lrow] = rb0.y;
        Bs[lk+2][lrow] = rb0.z; Bs[lk+3][lrow] = rb0.w;
        Bs[lk+4][lrow] = rb1.x; Bs[lk+5][lrow] = rb1.y;
        Bs[lk+6][lrow] = rb1.z; Bs[lk+7][lrow] = rb1.w;
        __syncthreads();

        int kn = k0 + 16;
        if (kn < I_DIM) {
            ra0 = avalid ? ld4(aptr + kn)     : z4;
            ra1 = avalid ? ld4(aptr + kn + 4) : z4;
            rb0 = ld4(bptr + kn);
            rb1 = ld4(bptr + kn + 4);
        }

        #pragma unroll
        for (int k = 0; k < 16; k++) {
            float a[8], b[8];
            #pragma unroll
            for (int i = 0; i < 8; i++) a[i] = As[k][ty*8 + i];
            #pragma unroll
            for (int j = 0; j < 8; j++) b[j] = Bs[k][tx*8 + j];
            #pragma unroll
            for (int i = 0; i < 8; i++)
                #pragma unroll
                for (int j = 0; j < 8; j++) acc[i][j] += a[i] * b[j];
        }
        __syncthreads();
    }

    // coef-scaled accumulate into output. Each out element receives exactly two
    // commutative atomic adds onto a zeroed location -> deterministic result.
    #pragma unroll
    for (int i = 0; i < 8; i++) {
        int m = m0 + ty*8 + i;
        if (m < cnt) {
            int   tkn = g_tok[off + m];
            float w   = g_cw [off + m];
            float* dst = out + (size_t)tkn * H_DIM + n0 + tx*8;
            #pragma unroll
            for (int j = 0; j < 8; j++)
                atomicAdd(dst + j, w * acc[i][j]);
        }
    }
}

// ---------------- launch ----------------
extern "C" void kernel_launch(void* const* d_in, const int* in_sizes, int n_in,
                              void* d_out, int out_size)
{
    const float* x      = (const float*)d_in[0];   // [T, H]
    const float* gate_w = (const float*)d_in[1];   // [E, H]
    const float* ws     = (const float*)d_in[2];   // [E, 2I, H]
    const float* w2s    = (const float*)d_in[3];   // [E, H, I]
    float* out = (float*)d_out;                    // [T, H]

    zero_kernel <<<1024, 256>>>(out);
    gate_kernel <<<T_TOK, 128>>>(x, gate_w);
    group_kernel<<<N_EXP, 256>>>();
    gemm1_kernel<<<dim3(2*I_DIM/128, T_TOK/128, N_EXP), 256>>>(x, ws);
    silu_kernel <<<(MAXP * (I_DIM/4)) / 256, 256>>>();
    gemm2_kernel<<<dim3(H_DIM/128, T_TOK/128, N_EXP), 256>>>(out, w2s);
}

// round 4
// speedup vs baseline: 1.4414x; 1.4414x over previous
#include <cuda_runtime.h>
#include <math.h>
#include <stdint.h>

#define T_TOK 4096
#define H_DIM 2048
#define I_DIM 2048
#define N_EXP 16
#define MAXP  (T_TOK*2)

#define BM 128
#define BK 32                       // fp32 k per chunk
#define NCH (H_DIM/BK)              // 64
#define ROWB 128                    // smem row bytes: 32 bf16 hi + 32 bf16 lo
#define A_BYTES (BM*ROWB)           // 16384
#define STG_BYTES (2*A_BYTES)       // 32768
#define SMEM_DYN 34560              // max(stage, ubuf 128*66*4=33792) padded

// ---------------- scratch ----------------
__device__ int   g_sel [T_TOK*2];
__device__ float g_selw[T_TOK*2];
__device__ int   g_cnt [N_EXP];
__device__ int   g_off [N_EXP+1];
__device__ int   g_tok [MAXP];
__device__ float g_cw  [MAXP];
__device__ int   g_pos [T_TOK*2];
__device__ float g_h   [(size_t)MAXP * I_DIM];   // silu(g)*u
__device__ float g_part[(size_t)MAXP * H_DIM];   // coef-scaled expert outputs

// ---------------- helpers ----------------
__device__ __forceinline__ uint32_t smem_u32(const void* p){
    uint32_t a;
    asm("{ .reg .u64 t; cvta.to.shared.u64 t, %1; cvt.u32.u64 %0, t; }" : "=r"(a) : "l"(p));
    return a;
}
__device__ __forceinline__ void st64(uint32_t a, uint32_t v0, uint32_t v1){
    asm volatile("st.shared.v2.b32 [%0], {%1,%2};" :: "r"(a), "r"(v0), "r"(v1) : "memory");
}
__device__ __forceinline__ void ldsm4(uint32_t& r0, uint32_t& r1, uint32_t& r2, uint32_t& r3,
                                      uint32_t addr){
    asm volatile("ldmatrix.sync.aligned.m8n8.x4.shared.b16 {%0,%1,%2,%3}, [%4];"
                 : "=r"(r0), "=r"(r1), "=r"(r2), "=r"(r3) : "r"(addr));
}
__device__ __forceinline__ void mma16816(float* d, uint32_t a0, uint32_t a1, uint32_t a2,
                                         uint32_t a3, uint32_t b0, uint32_t b1){
    asm volatile("mma.sync.aligned.m16n8k16.row.col.f32.bf16.bf16.f32 "
                 "{%0,%1,%2,%3}, {%4,%5,%6,%7}, {%8,%9}, {%0,%1,%2,%3};"
                 : "+f"(d[0]), "+f"(d[1]), "+f"(d[2]), "+f"(d[3])
                 : "r"(a0), "r"(a1), "r"(a2), "r"(a3), "r"(b0), "r"(b1));
}
// split fp32x4 -> packed bf16 hi (truncate) + bf16 lo (exact remainder, truncate)
__device__ __forceinline__ void split4(float4 v, uint32_t& h0, uint32_t& h1,
                                       uint32_t& l0, uint32_t& l1){
    uint32_t bx = __float_as_uint(v.x), by = __float_as_uint(v.y);
    uint32_t bz = __float_as_uint(v.z), bw = __float_as_uint(v.w);
    asm("prmt.b32 %0,%1,%2,0x7632;" : "=r"(h0) : "r"(bx), "r"(by));
    asm("prmt.b32 %0,%1,%2,0x7632;" : "=r"(h1) : "r"(bz), "r"(bw));
    float rx = v.x - __uint_as_float(h0 << 16);
    float ry = v.y - __uint_as_float(h0 & 0xffff0000u);
    float rz = v.z - __uint_as_float(h1 << 16);
    float rw = v.w - __uint_as_float(h1 & 0xffff0000u);
    uint32_t cx = __float_as_uint(rx), cy = __float_as_uint(ry);
    uint32_t cz = __float_as_uint(rz), cw = __float_as_uint(rw);
    asm("prmt.b32 %0,%1,%2,0x7632;" : "=r"(l0) : "r"(cx), "r"(cy));
    asm("prmt.b32 %0,%1,%2,0x7632;" : "=r"(l1) : "r"(cz), "r"(cw));
}

// ---------------- routing kernels ----------------
__global__ void init_kernel(){
    if (threadIdx.x < N_EXP) g_cnt[threadIdx.x] = 0;
}

__global__ void gate_kernel(const float* __restrict__ x, const float* __restrict__ gw){
    __shared__ float sx[H_DIM];
    __shared__ float slog[N_EXP];
    const int t = blockIdx.x;
    const float* xr = x + (size_t)t * H_DIM;
    for (int i = threadIdx.x; i < H_DIM; i += blockDim.x) sx[i] = xr[i];
    __syncthreads();

    const int warp = threadIdx.x >> 5, lane = threadIdx.x & 31;
    for (int e = warp; e < N_EXP; e += 4){
        const float* g = gw + (size_t)e * H_DIM;
        float s = 0.0f;
        for (int h = lane; h < H_DIM; h += 32) s += sx[h] * g[h];
        #pragma unroll
        for (int o = 16; o; o >>= 1) s += __shfl_xor_sync(0xffffffff, s, o);
        if (lane == 0) slog[e] = s;
    }
    __syncthreads();

    if (threadIdx.x == 0){
        int i0 = 0; float v0 = slog[0];
        for (int e = 1; e < N_EXP; e++) if (slog[e] > v0){ v0 = slog[e]; i0 = e; }
        int i1 = -1; float v1 = -INFINITY;
        for (int e = 0; e < N_EXP; e++) if (e != i0 && slog[e] > v1){ v1 = slog[e]; i1 = e; }
        float e1 = expf(v1 - v0);
        float inv = 1.0f / (1.0f + e1);
        g_sel [t*2]   = i0; g_selw[t*2]   = inv;
        g_sel [t*2+1] = i1; g_selw[t*2+1] = e1 * inv;
        atomicAdd(&g_cnt[i0], 1);
        atomicAdd(&g_cnt[i1], 1);
    }
}

__global__ void group_kernel(){
    const int e = blockIdx.x;
    __shared__ int sbase;
    __shared__ int scan[256];

    if (threadIdx.x == 0){
        int o = 0;
        for (int i = 0; i < e; i++) o += g_cnt[i];
        sbase = o;
        g_off[e] = o;
        if (e == N_EXP - 1) g_off[N_EXP] = o + g_cnt[e];
    }
    __syncthreads();
    int base = sbase;

    for (int t0 = 0; t0 < T_TOK; t0 += 256){
        int t = t0 + threadIdx.x;
        int pred = 0, which = 0; float w = 0.0f;
        int s0 = g_sel[t*2], s1 = g_sel[t*2+1];
        if      (s0 == e){ pred = 1; w = g_selw[t*2];   which = 0; }
        else if (s1 == e){ pred = 1; w = g_selw[t*2+1]; which = 1; }

        scan[threadIdx.x] = pred;
        __syncthreads();
        for (int o = 1; o < 256; o <<= 1){
            int v = 0;
            if (threadIdx.x >= o) v = scan[threadIdx.x - o];
            __syncthreads();
            scan[threadIdx.x] += v;
            __syncthreads();
        }
        int excl = scan[threadIdx.x] - pred;
        if (pred){
            int slot = base + excl;
            g_tok[slot] = t;
            g_cw [slot] = w;
            g_pos[t*2 + which] = slot;
        }
        int total = scan[255];
        __syncthreads();
        base += total;
    }
}

// ---------------- tensor-core grouped GEMM (mma.sync bf16 hi/lo 3-pass) --------
// MODE 0: B tile = 64 gate rows + matching 64 up rows; epilogue: silu(g)*u -> g_h
// MODE 1: part = (h @ w2_e^T) * coef -> g_part
template<int MODE>
__global__ void __launch_bounds__(256)
moe_gemm(const float* __restrict__ gA, const float* __restrict__ gB)
{
    const int e   = blockIdx.z;
    const int off = g_off[e];
    const int cnt = g_off[e+1] - off;
    const int m0  = blockIdx.y * BM;
    if (m0 >= cnt) return;
    const int n0  = blockIdx.x * ((MODE == 0) ? 64 : 128);

    extern __shared__ __align__(1024) char smem[];
    const uint32_t sb = smem_u32(smem);
    const int tid = threadIdx.x, wid = tid >> 5, lane = tid & 31;

    // ---- producer indexing: warp w owns A rows [w*16,+16) and B rows [w*16,+16)
    const int lrow4 = lane >> 3;       // 0..3 row within quad-group
    const int f4    = lane & 7;        // float4 index within 32-fp32 row

    const float* aptr[4]; bool aval[4];
    const float* bptr[4];
    uint32_t sa_hi[4], sa_lo[4], sbh[4], sbl[4];
    #pragma unroll
    for (int i = 0; i < 4; i++){
        int r  = wid*16 + i*4 + lrow4;     // local row 0..127
        int mr = m0 + r;
        bool v = (mr < cnt);
        aval[i] = v;
        if (MODE == 0)
            aptr[i] = gA + (size_t)(v ? g_tok[off + mr] : 0) * H_DIM + f4*4;
        else
            aptr[i] = g_h + (size_t)(off + (v ? mr : 0)) * I_DIM + f4*4;
        size_t grow;
        if (MODE == 0)
            grow = (size_t)e * (2*(size_t)I_DIM)
                 + (size_t)((r < 64) ? (n0 + r) : (I_DIM + n0 + (r - 64)));
        else
            grow = (size_t)e * H_DIM + (size_t)(n0 + r);
        bptr[i] = gB + grow * ((MODE == 0) ? H_DIM : I_DIM) + f4*4;

        uint32_t xo = (uint32_t)((r & 7) * 16);
        uint32_t rb = (uint32_t)(r * ROWB);
        sa_hi[i] = sb + rb + ((uint32_t)(f4*8)        ^ xo);
        sa_lo[i] = sb + rb + ((uint32_t)(64 + f4*8)   ^ xo);
        sbh[i]   = sb + A_BYTES + rb + ((uint32_t)(f4*8)      ^ xo);
        sbl[i]   = sb + A_BYTES + rb + ((uint32_t)(64 + f4*8) ^ xo);
    }

    // ---- consumer indexing: warp tile 64x32 at (wm*64, wn*32)
    const int wm = wid & 1, wn = wid >> 1;
    const int lrow8  = (lane & 7) + ((lane >> 3) & 1) * 8;  // row within 16-tile
    const int lc16   = ((lane >> 4) & 1) * 16;              // 16B chunk select
    const uint32_t xorv = (uint32_t)((lane & 7) * 16);      // swizzle (row&7)*16
    uint32_t aBase[4], bBase[2];
    #pragma unroll
    for (int mi = 0; mi < 4; mi++){
        int r = wm*64 + mi*16 + lrow8;
        aBase[mi] = sb + (uint32_t)(r * ROWB);
    }
    #pragma unroll
    for (int nb = 0; nb < 2; nb++){
        int r = wn*32 + nb*16 + lrow8;
        bBase[nb] = sb + A_BYTES + (uint32_t)(r * ROWB);
    }

    float acc[4][4][4];
    #pragma unroll
    for (int mi = 0; mi < 4; mi++)
        #pragma unroll
        for (int ni = 0; ni < 4; ni++)
            #pragma unroll
            for (int q = 0; q < 4; q++) acc[mi][ni][q] = 0.0f;

    const float4 z4 = make_float4(0.f, 0.f, 0.f, 0.f);
    float4 ra[4], rb[4];
    #pragma unroll
    for (int i = 0; i < 4; i++){
        ra[i] = aval[i] ? *(const float4*)(aptr[i]) : z4;
        rb[i] = *(const float4*)(bptr[i]);
    }

    for (int c = 0; c < NCH; c++){
        // STS current chunk (split to hi/lo bf16)
        #pragma unroll
        for (int i = 0; i < 4; i++){
            uint32_t h0, h1, l0, l1;
            split4(ra[i], h0, h1, l0, l1);
            st64(sa_hi[i], h0, h1); st64(sa_lo[i], l0, l1);
            split4(rb[i], h0, h1, l0, l1);
            st64(sbh[i], h0, h1);   st64(sbl[i], l0, l1);
        }
        __syncthreads();

        // prefetch next chunk
        if (c + 1 < NCH){
            int k = (c + 1) * BK;
            #pragma unroll
            for (int i = 0; i < 4; i++){
                ra[i] = aval[i] ? *(const float4*)(aptr[i] + k) : z4;
                rb[i] = *(const float4*)(bptr[i] + k);
            }
        }

        // compute: 2 k16 sub-steps, 3 passes each
        #pragma unroll
        for (int kc = 0; kc < 2; kc++){
            const uint32_t hiB = (uint32_t)(kc*32 + lc16);
            const uint32_t loB = hiB + 64;
            uint32_t bh[2][4], bl[2][4], af[4][4];
            #pragma unroll
            for (int nb = 0; nb < 2; nb++){
                ldsm4(bh[nb][0], bh[nb][1], bh[nb][2], bh[nb][3], bBase[nb] + (hiB ^ xorv));
                ldsm4(bl[nb][0], bl[nb][1], bl[nb][2], bl[nb][3], bBase[nb] + (loB ^ xorv));
            }
            #pragma unroll
            for (int mi = 0; mi < 4; mi++)
                ldsm4(af[mi][0], af[mi][1], af[mi][2], af[mi][3], aBase[mi] + (hiB ^ xorv));
            // hi*hi and hi*lo
            #pragma unroll
            for (int mi = 0; mi < 4; mi++)
                #pragma unroll
                for (int ni = 0; ni < 4; ni++){
                    const int nb = ni >> 1, hi2 = ni & 1;   // frag pair select
                    uint32_t b0h = hi2 ? bh[nb][1] : bh[nb][0];
                    uint32_t b1h = hi2 ? bh[nb][3] : bh[nb][2];
                    uint32_t b0l = hi2 ? bl[nb][1] : bl[nb][0];
                    uint32_t b1l = hi2 ? bl[nb][3] : bl[nb][2];
                    mma16816(acc[mi][ni], af[mi][0], af[mi][1], af[mi][2], af[mi][3], b0h, b1h);
                    mma16816(acc[mi][ni], af[mi][0], af[mi][1], af[mi][2], af[mi][3], b0l, b1l);
                }
            // lo*hi
            #pragma unroll
            for (int mi = 0; mi < 4; mi++)
                ldsm4(af[mi][0], af[mi][1], af[mi][2], af[mi][3], aBase[mi] + (loB ^ xorv));
            #pragma unroll
            for (int mi = 0; mi < 4; mi++)
                #pragma unroll
                for (int ni = 0; ni < 4; ni++){
                    const int nb = ni >> 1, hi2 = ni & 1;
                    uint32_t b0h = hi2 ? bh[nb][1] : bh[nb][0];
                    uint32_t b1h = hi2 ? bh[nb][3] : bh[nb][2];
                    mma16816(acc[mi][ni], af[mi][0], af[mi][1], af[mi][2], af[mi][3], b0h, b1h);
                }
        }
        __syncthreads();
    }

    // ---- epilogue ----
    const int row_l = lane >> 2;          // 0..7
    const int col2  = (lane & 3) * 2;

    if (MODE == 0){
        float* ub = (float*)smem;         // [128][66] fp32, reuses stage smem
        if (wn >= 2){                     // up warps stage their accs
            #pragma unroll
            for (int mi = 0; mi < 4; mi++)
                #pragma unroll
                for (int ni = 0; ni < 4; ni++){
                    int r  = wm*64 + mi*16 + row_l;
                    int cu = (wn - 2)*32 + ni*8 + col2;
                    ub[(r     )*66 + cu] = acc[mi][ni][0];
                    ub[(r     )*66 + cu + 1] = acc[mi][ni][1];
                    ub[(r + 8 )*66 + cu] = acc[mi][ni][2];
                    ub[(r + 8 )*66 + cu + 1] = acc[mi][ni][3];
                }
        }
        __syncthreads();
        if (wn < 2){                      // gate warps emit silu(g)*u
            #pragma unroll
            for (int mi = 0; mi < 4; mi++)
                #pragma unroll
                for (int ni = 0; ni < 4; ni++){
                    int r  = wm*64 + mi*16 + row_l;
                    int cg = wn*32 + ni*8 + col2;
                    #pragma unroll
                    for (int half = 0; half < 2; half++){
                        int rr = r + half*8;
                        int mg = m0 + rr;
                        if (mg < cnt){
                            float g0 = acc[mi][ni][half*2], g1 = acc[mi][ni][half*2+1];
                            float u0 = ub[rr*66 + cg], u1 = ub[rr*66 + cg + 1];
                            float2 o;
                            o.x = g0 / (1.0f + __expf(-g0)) * u0;
                            o.y = g1 / (1.0f + __expf(-g1)) * u1;
                            *(float2*)(g_h + (size_t)(off + mg) * I_DIM + n0 + cg) = o;
                        }
                    }
                }
        }
    } else {
        #pragma unroll
        for (int mi = 0; mi < 4; mi++)
            #pragma unroll
            for (int ni = 0; ni < 4; ni++){
                int r = wm*64 + mi*16 + row_l;
                int cc = n0 + wn*32 + ni*8 + col2;
                #pragma unroll
                for (int half = 0; half < 2; half++){
                    int rr = r + half*8;
                    int mg = m0 + rr;
                    if (mg < cnt){
                        float w = g_cw[off + mg];
                        float2 o;
                        o.x = w * acc[mi][ni][half*2];
                        o.y = w * acc[mi][ni][half*2+1];
                        *(float2*)(g_part + (size_t)(off + mg) * H_DIM + cc) = o;
                    }
                }
            }
    }
}

// ---------------- combine two expert partials per token ----------------
__global__ void combine_kernel(float* __restrict__ out){
    int idx = blockIdx.x * blockDim.x + threadIdx.x;
    int t  = idx >> 9;
    int c4 = (idx & 511) * 4;
    int p0 = g_pos[t*2], p1 = g_pos[t*2+1];
    float4 a = *(const float4*)(g_part + (size_t)p0 * H_DIM + c4);
    float4 b = *(const float4*)(g_part + (size_t)p1 * H_DIM + c4);
    float4 o;
    o.x = a.x + b.x; o.y = a.y + b.y; o.z = a.z + b.z; o.w = a.w + b.w;
    *(float4*)(out + (size_t)t * H_DIM + c4) = o;
}

// ---------------- launch ----------------
extern "C" void kernel_launch(void* const* d_in, const int* in_sizes, int n_in,
                              void* d_out, int out_size)
{
    const float* x      = (const float*)d_in[0];   // [T, H]
    const float* gate_w = (const float*)d_in[1];   // [E, H]
    const float* ws     = (const float*)d_in[2];   // [E, 2I, H]
    const float* w2s    = (const float*)d_in[3];   // [E, H, I]
    float* out = (float*)d_out;                    // [T, H]

    init_kernel <<<1, 32>>>();
    gate_kernel <<<T_TOK, 128>>>(x, gate_w);
    group_kernel<<<N_EXP, 256>>>();
    moe_gemm<0> <<<dim3(I_DIM/64,  T_TOK/BM, N_EXP), 256, SMEM_DYN>>>(x, ws);
    moe_gemm<1> <<<dim3(H_DIM/128, T_TOK/BM, N_EXP), 256, SMEM_DYN>>>(x, w2s);
    combine_kernel<<<(T_TOK*H_DIM/4)/256, 256>>>(out);
}

// round 5
// speedup vs baseline: 1.8977x; 1.3165x over previous
#include <cuda_runtime.h>
#include <cuda_bf16.h>
#include <math.h>
#include <stdint.h>

#define T_TOK 4096
#define H_DIM 2048
#define I_DIM 2048
#define N_EXP 16
#define MAXP  (T_TOK*2)

#define BM 128
#define BK 32                       // fp32 k per chunk
#define NCH 64                      // 2048/32
#define ROWB 128                    // smem row: 32 bf16 hi + 32 bf16 lo
#define A_BYTES (BM*ROWB)           // 16 KB
#define STG_BYTES (2*A_BYTES)       // 32 KB
#define NSTAGE 4
#define SMEM_DYN (NSTAGE*STG_BYTES) // 128 KB

// ---------------- scratch ----------------
__device__ int   g_sel [T_TOK*2];
__device__ float g_selw[T_TOK*2];
__device__ int   g_cnt [N_EXP];
__device__ int   g_off [N_EXP+1];
__device__ int   g_tok [MAXP];
__device__ float g_cw  [MAXP];
__device__ int   g_pos [T_TOK*2];
__device__ float g_part[(size_t)MAXP * H_DIM];

// pre-split bf16 hi/lo copies
__device__ __align__(16) __nv_bfloat16 g_xhi [(size_t)T_TOK * H_DIM];
__device__ __align__(16) __nv_bfloat16 g_xlo [(size_t)T_TOK * H_DIM];
__device__ __align__(16) __nv_bfloat16 g_wshi[(size_t)N_EXP * 2 * I_DIM * H_DIM];
__device__ __align__(16) __nv_bfloat16 g_wslo[(size_t)N_EXP * 2 * I_DIM * H_DIM];
__device__ __align__(16) __nv_bfloat16 g_w2hi[(size_t)N_EXP * H_DIM * I_DIM];
__device__ __align__(16) __nv_bfloat16 g_w2lo[(size_t)N_EXP * H_DIM * I_DIM];
__device__ __align__(16) __nv_bfloat16 g_hhi [(size_t)MAXP * I_DIM];
__device__ __align__(16) __nv_bfloat16 g_hlo [(size_t)MAXP * I_DIM];

// ---------------- helpers ----------------
__device__ __forceinline__ uint32_t smem_u32(const void* p){
    uint32_t a;
    asm("{ .reg .u64 t; cvta.to.shared.u64 t, %1; cvt.u32.u64 %0, t; }" : "=r"(a) : "l"(p));
    return a;
}
__device__ __forceinline__ void ldsm4(uint32_t& r0, uint32_t& r1, uint32_t& r2, uint32_t& r3,
                                      uint32_t addr){
    asm volatile("ldmatrix.sync.aligned.m8n8.x4.shared.b16 {%0,%1,%2,%3}, [%4];"
                 : "=r"(r0), "=r"(r1), "=r"(r2), "=r"(r3) : "r"(addr));
}
__device__ __forceinline__ void mma16816(float* d, uint32_t a0, uint32_t a1, uint32_t a2,
                                         uint32_t a3, uint32_t b0, uint32_t b1){
    asm volatile("mma.sync.aligned.m16n8k16.row.col.f32.bf16.bf16.f32 "
                 "{%0,%1,%2,%3}, {%4,%5,%6,%7}, {%8,%9}, {%0,%1,%2,%3};"
                 : "+f"(d[0]), "+f"(d[1]), "+f"(d[2]), "+f"(d[3])
                 : "r"(a0), "r"(a1), "r"(a2), "r"(a3), "r"(b0), "r"(b1));
}
#define CPA(dst, src) \
    asm volatile("cp.async.cg.shared.global [%0], [%1], 16;" :: "r"(dst), "l"(src))
#define CP_COMMIT() asm volatile("cp.async.commit_group;" ::: "memory")
#define CP_WAIT2()  asm volatile("cp.async.wait_group 2;" ::: "memory")
#define CP_WAIT0()  asm volatile("cp.async.wait_group 0;" ::: "memory")

// split fp32x4 -> packed bf16 hi (truncate) + bf16 lo (exact remainder, truncate)
__device__ __forceinline__ void split4(float4 v, uint32_t& h0, uint32_t& h1,
                                       uint32_t& l0, uint32_t& l1){
    uint32_t bx = __float_as_uint(v.x), by = __float_as_uint(v.y);
    uint32_t bz = __float_as_uint(v.z), bw = __float_as_uint(v.w);
    asm("prmt.b32 %0,%1,%2,0x7632;" : "=r"(h0) : "r"(bx), "r"(by));
    asm("prmt.b32 %0,%1,%2,0x7632;" : "=r"(h1) : "r"(bz), "r"(bw));
    float rx = v.x - __uint_as_float(h0 << 16);
    float ry = v.y - __uint_as_float(h0 & 0xffff0000u);
    float rz = v.z - __uint_as_float(h1 << 16);
    float rw = v.w - __uint_as_float(h1 & 0xffff0000u);
    uint32_t cx = __float_as_uint(rx), cy = __float_as_uint(ry);
    uint32_t cz = __float_as_uint(rz), cw = __float_as_uint(rw);
    asm("prmt.b32 %0,%1,%2,0x7632;" : "=r"(l0) : "r"(cx), "r"(cy));
    asm("prmt.b32 %0,%1,%2,0x7632;" : "=r"(l1) : "r"(cz), "r"(cw));
}
__device__ __forceinline__ void split2(float a, float b, uint32_t& hi, uint32_t& lo){
    uint32_t ba = __float_as_uint(a), bb = __float_as_uint(b);
    asm("prmt.b32 %0,%1,%2,0x7632;" : "=r"(hi) : "r"(ba), "r"(bb));
    float ra = a - __uint_as_float(hi << 16);
    float rb = b - __uint_as_float(hi & 0xffff0000u);
    uint32_t ca = __float_as_uint(ra), cb = __float_as_uint(rb);
    asm("prmt.b32 %0,%1,%2,0x7632;" : "=r"(lo) : "r"(ca), "r"(cb));
}

// ---------------- pre-split kernels ----------------
template<int W>
__global__ void split_kernel(const float4* __restrict__ src, int n4){
    int i = blockIdx.x * blockDim.x + threadIdx.x;
    if (i >= n4) return;
    __nv_bfloat16* dhi = (W == 0) ? g_xhi : (W == 1) ? g_wshi : g_w2hi;
    __nv_bfloat16* dlo = (W == 0) ? g_xlo : (W == 1) ? g_wslo : g_w2lo;
    float4 v = src[i];
    uint32_t h0, h1, l0, l1;
    split4(v, h0, h1, l0, l1);
    reinterpret_cast<uint2*>(dhi)[i] = make_uint2(h0, h1);
    reinterpret_cast<uint2*>(dlo)[i] = make_uint2(l0, l1);
}

// ---------------- routing kernels ----------------
__global__ void init_kernel(){
    if (threadIdx.x < N_EXP) g_cnt[threadIdx.x] = 0;
}

__global__ void gate_kernel(const float* __restrict__ x, const float* __restrict__ gw){
    __shared__ float sx[H_DIM];
    __shared__ float slog[N_EXP];
    const int t = blockIdx.x;
    const float* xr = x + (size_t)t * H_DIM;
    for (int i = threadIdx.x; i < H_DIM; i += blockDim.x) sx[i] = xr[i];
    __syncthreads();

    const int warp = threadIdx.x >> 5, lane = threadIdx.x & 31;
    for (int e = warp; e < N_EXP; e += 4){
        const float* g = gw + (size_t)e * H_DIM;
        float s = 0.0f;
        for (int h = lane; h < H_DIM; h += 32) s += sx[h] * g[h];
        #pragma unroll
        for (int o = 16; o; o >>= 1) s += __shfl_xor_sync(0xffffffff, s, o);
        if (lane == 0) slog[e] = s;
    }
    __syncthreads();

    if (threadIdx.x == 0){
        int i0 = 0; float v0 = slog[0];
        for (int e = 1; e < N_EXP; e++) if (slog[e] > v0){ v0 = slog[e]; i0 = e; }
        int i1 = -1; float v1 = -INFINITY;
        for (int e = 0; e < N_EXP; e++) if (e != i0 && slog[e] > v1){ v1 = slog[e]; i1 = e; }
        float e1 = expf(v1 - v0);
        float inv = 1.0f / (1.0f + e1);
        g_sel [t*2]   = i0; g_selw[t*2]   = inv;
        g_sel [t*2+1] = i1; g_selw[t*2+1] = e1 * inv;
        atomicAdd(&g_cnt[i0], 1);
        atomicAdd(&g_cnt[i1], 1);
    }
}

__global__ void group_kernel(){
    const int e = blockIdx.x;
    __shared__ int sbase;
    __shared__ int scan[256];

    if (threadIdx.x == 0){
        int o = 0;
        for (int i = 0; i < e; i++) o += g_cnt[i];
        sbase = o;
        g_off[e] = o;
        if (e == N_EXP - 1) g_off[N_EXP] = o + g_cnt[e];
    }
    __syncthreads();
    int base = sbase;

    for (int t0 = 0; t0 < T_TOK; t0 += 256){
        int t = t0 + threadIdx.x;
        int pred = 0, which = 0; float w = 0.0f;
        int s0 = g_sel[t*2], s1 = g_sel[t*2+1];
        if      (s0 == e){ pred = 1; w = g_selw[t*2];   which = 0; }
        else if (s1 == e){ pred = 1; w = g_selw[t*2+1]; which = 1; }

        scan[threadIdx.x] = pred;
        __syncthreads();
        for (int o = 1; o < 256; o <<= 1){
            int v = 0;
            if (threadIdx.x >= o) v = scan[threadIdx.x - o];
            __syncthreads();
            scan[threadIdx.x] += v;
            __syncthreads();
        }
        int excl = scan[threadIdx.x] - pred;
        if (pred){
            int slot = base + excl;
            g_tok[slot] = t;
            g_cw [slot] = w;
            g_pos[t*2 + which] = slot;
        }
        int total = scan[255];
        __syncthreads();
        base += total;
    }
}

// ---------------- tensor-core grouped GEMM (cp.async 4-stage, bf16 hi/lo 3-pass)
// MODE 0: B tile = 64 gate rows + matching 64 up rows; epilogue silu(g)*u -> g_hhi/lo
// MODE 1: part = (h @ w2_e^T) * coef -> g_part
template<int MODE>
__global__ void __launch_bounds__(256)
moe_gemm()
{
    const int e   = blockIdx.z;
    const int off = g_off[e];
    const int cnt = g_off[e+1] - off;
    const int m0  = blockIdx.y * BM;
    if (m0 >= cnt) return;
    const int n0  = blockIdx.x * ((MODE == 0) ? 64 : 128);

    extern __shared__ __align__(1024) char smem[];
    const uint32_t sb = smem_u32(smem);
    const int tid = threadIdx.x, wid = tid >> 5, lane = tid & 31;

    // ---- producer: thread t owns row tid>>1 (A and B), half tid&1 (32B hi + 32B lo)
    const int prow  = tid >> 1;
    const int phalf = tid & 1;
    const __nv_bfloat16 *pa_hi, *pa_lo, *pb_hi, *pb_lo;
    {
        int mr = m0 + prow;
        bool v = (mr < cnt);
        if (MODE == 0){
            size_t ar = (size_t)(v ? g_tok[off + mr] : 0) * H_DIM;
            pa_hi = g_xhi + ar; pa_lo = g_xlo + ar;
            size_t br = (size_t)e * (2*(size_t)I_DIM)
                      + (size_t)((prow < 64) ? (n0 + prow) : (I_DIM + n0 + (prow - 64)));
            pb_hi = g_wshi + br * H_DIM; pb_lo = g_wslo + br * H_DIM;
        } else {
            size_t ar = (size_t)(off + (v ? mr : 0)) * I_DIM;
            pa_hi = g_hhi + ar; pa_lo = g_hlo + ar;
            size_t br = (size_t)e * H_DIM + (size_t)(n0 + prow);
            pb_hi = g_w2hi + br * I_DIM; pb_lo = g_w2lo + br * I_DIM;
        }
    }
    const uint32_t psw = (uint32_t)((prow & 7) * 16);
    const uint32_t d0  = (uint32_t)(prow*ROWB) + (((uint32_t)(phalf*32))      ^ psw);
    const uint32_t d1  = (uint32_t)(prow*ROWB) + (((uint32_t)(phalf*32 + 16)) ^ psw);
    const uint32_t d0l = (uint32_t)(prow*ROWB) + (((uint32_t)(64 + phalf*32))      ^ psw);
    const uint32_t d1l = (uint32_t)(prow*ROWB) + (((uint32_t)(64 + phalf*32 + 16)) ^ psw);

    #define ISSUE(c) do { \
        uint32_t stg = sb + (uint32_t)(((c) & 3) * STG_BYTES); \
        int k0 = (c)*BK + phalf*16; \
        CPA(stg + d0,            pa_hi + k0);     \
        CPA(stg + d1,            pa_hi + k0 + 8); \
        CPA(stg + d0l,           pa_lo + k0);     \
        CPA(stg + d1l,           pa_lo + k0 + 8); \
        CPA(stg + A_BYTES + d0,  pb_hi + k0);     \
        CPA(stg + A_BYTES + d1,  pb_hi + k0 + 8); \
        CPA(stg + A_BYTES + d0l, pb_lo + k0);     \
        CPA(stg + A_BYTES + d1l, pb_lo + k0 + 8); \
    } while(0)

    // ---- consumer indexing: warp tile 64x32 at (wm*64, wn*32)
    const int wm = wid & 1, wn = wid >> 1;
    const int lrow8 = (lane & 7) + ((lane >> 3) & 1) * 8;
    const int lc16  = ((lane >> 4) & 1) * 16;
    const uint32_t xorv = (uint32_t)((lane & 7) * 16);
    uint32_t aOff[4], bOff[2];
    #pragma unroll
    for (int mi = 0; mi < 4; mi++)
        aOff[mi] = (uint32_t)((wm*64 + mi*16 + lrow8) * ROWB);
    #pragma unroll
    for (int nb = 0; nb < 2; nb++)
        bOff[nb] = (uint32_t)(A_BYTES + (wn*32 + nb*16 + lrow8) * ROWB);

    float acc[4][4][4];
    #pragma unroll
    for (int mi = 0; mi < 4; mi++)
        #pragma unroll
        for (int ni = 0; ni < 4; ni++)
            #pragma unroll
            for (int q = 0; q < 4; q++) acc[mi][ni][q] = 0.0f;

    // ---- pipeline ----
    #pragma unroll
    for (int c = 0; c < NSTAGE-1; c++){ ISSUE(c); CP_COMMIT(); }

    for (int c = 0; c < NCH; c++){
        CP_WAIT2();
        __syncthreads();
        if (c + NSTAGE-1 < NCH) ISSUE(c + NSTAGE-1);
        CP_COMMIT();

        const uint32_t stg = sb + (uint32_t)((c & 3) * STG_BYTES);
        #pragma unroll
        for (int kc = 0; kc < 2; kc++){
            const uint32_t hiB = (uint32_t)(kc*32 + lc16);
            const uint32_t loB = hiB + 64;
            uint32_t bh[2][4], bl[2][4], af[4][4];
            #pragma unroll
            for (int nb = 0; nb < 2; nb++){
                ldsm4(bh[nb][0], bh[nb][1], bh[nb][2], bh[nb][3], stg + bOff[nb] + (hiB ^ xorv));
                ldsm4(bl[nb][0], bl[nb][1], bl[nb][2], bl[nb][3], stg + bOff[nb] + (loB ^ xorv));
            }
            #pragma unroll
            for (int mi = 0; mi < 4; mi++)
                ldsm4(af[mi][0], af[mi][1], af[mi][2], af[mi][3], stg + aOff[mi] + (hiB ^ xorv));
            #pragma unroll
            for (int mi = 0; mi < 4; mi++)
                #pragma unroll
                for (int ni = 0; ni < 4; ni++){
                    const int nb = ni >> 1, hi2 = ni & 1;
                    uint32_t b0h = hi2 ? bh[nb][1] : bh[nb][0];
                    uint32_t b1h = hi2 ? bh[nb][3] : bh[nb][2];
                    uint32_t b0l = hi2 ? bl[nb][1] : bl[nb][0];
                    uint32_t b1l = hi2 ? bl[nb][3] : bl[nb][2];
                    mma16816(acc[mi][ni], af[mi][0], af[mi][1], af[mi][2], af[mi][3], b0h, b1h);
                    mma16816(acc[mi][ni], af[mi][0], af[mi][1], af[mi][2], af[mi][3], b0l, b1l);
                }
            #pragma unroll
            for (int mi = 0; mi < 4; mi++)
                ldsm4(af[mi][0], af[mi][1], af[mi][2], af[mi][3], stg + aOff[mi] + (loB ^ xorv));
            #pragma unroll
            for (int mi = 0; mi < 4; mi++)
                #pragma unroll
                for (int ni = 0; ni < 4; ni++){
                    const int nb = ni >> 1, hi2 = ni & 1;
                    uint32_t b0h = hi2 ? bh[nb][1] : bh[nb][0];
                    uint32_t b1h = hi2 ? bh[nb][3] : bh[nb][2];
                    mma16816(acc[mi][ni], af[mi][0], af[mi][1], af[mi][2], af[mi][3], b0h, b1h);
                }
        }
    }

    CP_WAIT0();
    __syncthreads();

    // ---- epilogue ----
    const int row_l = lane >> 2;
    const int col2  = (lane & 3) * 2;

    if (MODE == 0){
        float* ub = (float*)smem;          // [128][66] fp32, reuses stage smem
        if (wn >= 2){
            #pragma unroll
            for (int mi = 0; mi < 4; mi++)
                #pragma unroll
                for (int ni = 0; ni < 4; ni++){
                    int r  = wm*64 + mi*16 + row_l;
                    int cu = (wn - 2)*32 + ni*8 + col2;
                    ub[(r    )*66 + cu]     = acc[mi][ni][0];
                    ub[(r    )*66 + cu + 1] = acc[mi][ni][1];
                    ub[(r + 8)*66 + cu]     = acc[mi][ni][2];
                    ub[(r + 8)*66 + cu + 1] = acc[mi][ni][3];
                }
        }
        __syncthreads();
        if (wn < 2){
            #pragma unroll
            for (int mi = 0; mi < 4; mi++)
                #pragma unroll
                for (int ni = 0; ni < 4; ni++){
                    int r  = wm*64 + mi*16 + row_l;
                    int cg = wn*32 + ni*8 + col2;
                    #pragma unroll
                    for (int half = 0; half < 2; half++){
                        int rr = r + half*8;
                        int mg = m0 + rr;
                        if (mg < cnt){
                            float g0 = acc[mi][ni][half*2], g1 = acc[mi][ni][half*2+1];
                            float u0 = ub[rr*66 + cg], u1 = ub[rr*66 + cg + 1];
                            float h0 = g0 / (1.0f + __expf(-g0)) * u0;
                            float h1 = g1 / (1.0f + __expf(-g1)) * u1;
                            uint32_t hi, lo;
                            split2(h0, h1, hi, lo);
                            size_t idx = (size_t)(off + mg) * I_DIM + n0 + cg;
                            *(uint32_t*)(g_hhi + idx) = hi;
                            *(uint32_t*)(g_hlo + idx) = lo;
                        }
                    }
                }
        }
    } else {
        #pragma unroll
        for (int mi = 0; mi < 4; mi++)
            #pragma unroll
            for (int ni = 0; ni < 4; ni++){
                int r  = wm*64 + mi*16 + row_l;
                int cc = n0 + wn*32 + ni*8 + col2;
                #pragma unroll
                for (int half = 0; half < 2; half++){
                    int rr = r + half*8;
                    int mg = m0 + rr;
                    if (mg < cnt){
                        float w = g_cw[off + mg];
                        float2 o;
                        o.x = w * acc[mi][ni][half*2];
                        o.y = w * acc[mi][ni][half*2+1];
                        *(float2*)(g_part + (size_t)(off + mg) * H_DIM + cc) = o;
                    }
                }
            }
    }
    #undef ISSUE
}

// ---------------- combine two expert partials per token ----------------
__global__ void combine_kernel(float* __restrict__ out){
    int idx = blockIdx.x * blockDim.x + threadIdx.x;
    int t  = idx >> 9;
    int c4 = (idx & 511) * 4;
    int p0 = g_pos[t*2], p1 = g_pos[t*2+1];
    float4 a = *(const float4*)(g_part + (size_t)p0 * H_DIM + c4);
    float4 b = *(const float4*)(g_part + (size_t)p1 * H_DIM + c4);
    float4 o;
    o.x = a.x + b.x; o.y = a.y + b.y; o.z = a.z + b.z; o.w = a.w + b.w;
    *(float4*)(out + (size_t)t * H_DIM + c4) = o;
}

// ---------------- launch ----------------
extern "C" void kernel_launch(void* const* d_in, const int* in_sizes, int n_in,
                              void* d_out, int out_size)
{
    const float* x      = (const float*)d_in[0];   // [T, H]
    const float* gate_w = (const float*)d_in[1];   // [E, H]
    const float* ws     = (const float*)d_in[2];   // [E, 2I, H]
    const float* w2s    = (const float*)d_in[3];   // [E, H, I]
    float* out = (float*)d_out;                    // [T, H]

    static int attr_done = 0;
    cudaFuncSetAttribute(moe_gemm<0>, cudaFuncAttributeMaxDynamicSharedMemorySize, SMEM_DYN);
    cudaFuncSetAttribute(moe_gemm<1>, cudaFuncAttributeMaxDynamicSharedMemorySize, SMEM_DYN);
    (void)attr_done;

    const int n4x  = T_TOK * H_DIM / 4;
    const int n4ws = N_EXP * 2 * I_DIM * (H_DIM / 4);
    const int n4w2 = N_EXP * H_DIM * (I_DIM / 4);

    split_kernel<0><<<n4x  / 256, 256>>>((const float4*)x,   n4x);
    split_kernel<1><<<n4ws / 256, 256>>>((const float4*)ws,  n4ws);
    split_kernel<2><<<n4w2 / 256, 256>>>((const float4*)w2s, n4w2);

    init_kernel <<<1, 32>>>();
    gate_kernel <<<T_TOK, 128>>>(x, gate_w);
    group_kernel<<<N_EXP, 256>>>();
    moe_gemm<0> <<<dim3(I_DIM/64,  T_TOK/BM, N_EXP), 256, SMEM_DYN>>>();
    moe_gemm<1> <<<dim3(H_DIM/128, T_TOK/BM, N_EXP), 256, SMEM_DYN>>>();
    combine_kernel<<<(T_TOK*H_DIM/4)/256, 256>>>(out);
}

// round 12
// speedup vs baseline: 2.1050x; 1.1093x over previous
#include <cuda_runtime.h>
#include <cuda_bf16.h>
#include <math.h>
#include <stdint.h>

#define T_TOK 4096
#define H_DIM 2048
#define I_DIM 2048
#define N_EXP 16
#define MAXP  (T_TOK*2)

#define BM 64                       // m rows per CTA
#define BK 32                       // fp32 k per chunk
#define NCH 64                      // 2048/32
#define ROWB 128                    // smem row: 32 bf16 hi + 32 bf16 lo
#define A_BYTES (BM*ROWB)           // 8 KB
#define B_BYTES (128*ROWB)          // 16 KB
#define STG_BYTES (A_BYTES+B_BYTES) // 24 KB
#define NSTAGE 4
#define SMEM_DYN (NSTAGE*STG_BYTES) // 96 KB -> 2 CTAs/SM

// ---------------- scratch ----------------
__device__ int   g_sel [T_TOK*2];
__device__ float g_selw[T_TOK*2];
__device__ int   g_cnt [N_EXP];
__device__ int   g_off [N_EXP+1];
__device__ int   g_tok [MAXP];
__device__ float g_cw  [MAXP];

// pre-split bf16 hi/lo copies (R5-proven format)
__device__ __align__(16) __nv_bfloat16 g_xhi [(size_t)T_TOK * H_DIM];
__device__ __align__(16) __nv_bfloat16 g_xlo [(size_t)T_TOK * H_DIM];
__device__ __align__(16) __nv_bfloat16 g_wshi[(size_t)N_EXP * 2 * I_DIM * H_DIM];
__device__ __align__(16) __nv_bfloat16 g_wslo[(size_t)N_EXP * 2 * I_DIM * H_DIM];
__device__ __align__(16) __nv_bfloat16 g_w2hi[(size_t)N_EXP * H_DIM * I_DIM];
__device__ __align__(16) __nv_bfloat16 g_w2lo[(size_t)N_EXP * H_DIM * I_DIM];
__device__ __align__(16) __nv_bfloat16 g_hhi [(size_t)MAXP * I_DIM];
__device__ __align__(16) __nv_bfloat16 g_hlo [(size_t)MAXP * I_DIM];

// ---------------- helpers ----------------
__device__ __forceinline__ uint32_t smem_u32(const void* p){
    uint32_t a;
    asm("{ .reg .u64 t; cvta.to.shared.u64 t, %1; cvt.u32.u64 %0, t; }" : "=r"(a) : "l"(p));
    return a;
}
__device__ __forceinline__ void ldsm4(uint32_t* r, uint32_t addr){
    asm volatile("ldmatrix.sync.aligned.m8n8.x4.shared.b16 {%0,%1,%2,%3}, [%4];"
                 : "=r"(r[0]), "=r"(r[1]), "=r"(r[2]), "=r"(r[3]) : "r"(addr));
}
__device__ __forceinline__ void mma_bf16(float* d, const uint32_t* a, uint32_t b0, uint32_t b1){
    asm volatile("mma.sync.aligned.m16n8k16.row.col.f32.bf16.bf16.f32 "
                 "{%0,%1,%2,%3}, {%4,%5,%6,%7}, {%8,%9}, {%0,%1,%2,%3};"
                 : "+f"(d[0]), "+f"(d[1]), "+f"(d[2]), "+f"(d[3])
                 : "r"(a[0]), "r"(a[1]), "r"(a[2]), "r"(a[3]), "r"(b0), "r"(b1));
}
#define CPA(dst, src) \
    asm volatile("cp.async.cg.shared.global [%0], [%1], 16;" :: "r"(dst), "l"(src))
#define CP_COMMIT() asm volatile("cp.async.commit_group;" ::: "memory")
#define CP_WAIT2()  asm volatile("cp.async.wait_group 2;" ::: "memory")
#define CP_WAIT0()  asm volatile("cp.async.wait_group 0;" ::: "memory")

// split fp32x4 -> packed bf16 hi (truncate) + bf16 lo (exact remainder, truncate)
__device__ __forceinline__ void split4(float4 v, uint32_t& h0, uint32_t& h1,
                                       uint32_t& l0, uint32_t& l1){
    uint32_t bx = __float_as_uint(v.x), by = __float_as_uint(v.y);
    uint32_t bz = __float_as_uint(v.z), bw = __float_as_uint(v.w);
    asm("prmt.b32 %0,%1,%2,0x7632;" : "=r"(h0) : "r"(bx), "r"(by));
    asm("prmt.b32 %0,%1,%2,0x7632;" : "=r"(h1) : "r"(bz), "r"(bw));
    float rx = v.x - __uint_as_float(h0 << 16);
    float ry = v.y - __uint_as_float(h0 & 0xffff0000u);
    float rz = v.z - __uint_as_float(h1 << 16);
    float rw = v.w - __uint_as_float(h1 & 0xffff0000u);
    uint32_t cx = __float_as_uint(rx), cy = __float_as_uint(ry);
    uint32_t cz = __float_as_uint(rz), cw = __float_as_uint(rw);
    asm("prmt.b32 %0,%1,%2,0x7632;" : "=r"(l0) : "r"(cx), "r"(cy));
    asm("prmt.b32 %0,%1,%2,0x7632;" : "=r"(l1) : "r"(cz), "r"(cw));
}
__device__ __forceinline__ void split2(float a, float b, uint32_t& hi, uint32_t& lo){
    uint32_t ba = __float_as_uint(a), bb = __float_as_uint(b);
    asm("prmt.b32 %0,%1,%2,0x7632;" : "=r"(hi) : "r"(ba), "r"(bb));
    float ra = a - __uint_as_float(hi << 16);
    float rb = b - __uint_as_float(hi & 0xffff0000u);
    uint32_t ca = __float_as_uint(ra), cb = __float_as_uint(rb);
    asm("prmt.b32 %0,%1,%2,0x7632;" : "=r"(lo) : "r"(ca), "r"(cb));
}

// ---------------- pre-split kernels (R5 verbatim) ----------------
template<int W>
__global__ void split_kernel(const float4* __restrict__ src, int n4){
    int i = blockIdx.x * blockDim.x + threadIdx.x;
    if (i >= n4) return;
    __nv_bfloat16* dhi = (W == 0) ? g_xhi : (W == 1) ? g_wshi : g_w2hi;
    __nv_bfloat16* dlo = (W == 0) ? g_xlo : (W == 1) ? g_wslo : g_w2lo;
    float4 v = src[i];
    uint32_t h0, h1, l0, l1;
    split4(v, h0, h1, l0, l1);
    reinterpret_cast<uint2*>(dhi)[i] = make_uint2(h0, h1);
    reinterpret_cast<uint2*>(dlo)[i] = make_uint2(l0, l1);
}

// ---------------- zero output + counters ----------------
__global__ void zero_kernel(float4* __restrict__ out){
    int i = blockIdx.x * blockDim.x + threadIdx.x;   // T*H/4 threads
    out[i] = make_float4(0.f, 0.f, 0.f, 0.f);
    if (blockIdx.x == 0 && threadIdx.x < N_EXP) g_cnt[threadIdx.x] = 0;
}

// ---------------- routing kernels (R5 verbatim) ----------------
__global__ void gate_kernel(const float* __restrict__ x, const float* __restrict__ gw){
    __shared__ float sx[H_DIM];
    __shared__ float slog[N_EXP];
    const int t = blockIdx.x;
    const float* xr = x + (size_t)t * H_DIM;
    for (int i = threadIdx.x; i < H_DIM; i += blockDim.x) sx[i] = xr[i];
    __syncthreads();

    const int warp = threadIdx.x >> 5, lane = threadIdx.x & 31;
    for (int e = warp; e < N_EXP; e += 4){
        const float* g = gw + (size_t)e * H_DIM;
        float s = 0.0f;
        for (int h = lane; h < H_DIM; h += 32) s += sx[h] * g[h];
        #pragma unroll
        for (int o = 16; o; o >>= 1) s += __shfl_xor_sync(0xffffffff, s, o);
        if (lane == 0) slog[e] = s;
    }
    __syncthreads();

    if (threadIdx.x == 0){
        int i0 = 0; float v0 = slog[0];
        for (int e = 1; e < N_EXP; e++) if (slog[e] > v0){ v0 = slog[e]; i0 = e; }
        int i1 = -1; float v1 = -INFINITY;
        for (int e = 0; e < N_EXP; e++) if (e != i0 && slog[e] > v1){ v1 = slog[e]; i1 = e; }
        float e1 = expf(v1 - v0);
        float inv = 1.0f / (1.0f + e1);
        g_sel [t*2]   = i0; g_selw[t*2]   = inv;
        g_sel [t*2+1] = i1; g_selw[t*2+1] = e1 * inv;
        atomicAdd(&g_cnt[i0], 1);
        atomicAdd(&g_cnt[i1], 1);
    }
}

__global__ void group_kernel(){
    const int e = blockIdx.x;
    __shared__ int sbase;
    __shared__ int scan[256];

    if (threadIdx.x == 0){
        int o = 0;
        for (int i = 0; i < e; i++) o += g_cnt[i];
        sbase = o;
        g_off[e] = o;
        if (e == N_EXP - 1) g_off[N_EXP] = o + g_cnt[e];
    }
    __syncthreads();
    int base = sbase;

    for (int t0 = 0; t0 < T_TOK; t0 += 256){
        int t = t0 + threadIdx.x;
        int pred = 0; float w = 0.0f;
        int s0 = g_sel[t*2], s1 = g_sel[t*2+1];
        if      (s0 == e){ pred = 1; w = g_selw[t*2];   }
        else if (s1 == e){ pred = 1; w = g_selw[t*2+1]; }

        scan[threadIdx.x] = pred;
        __syncthreads();
        for (int o = 1; o < 256; o <<= 1){
            int v = 0;
            if (threadIdx.x >= o) v = scan[threadIdx.x - o];
            __syncthreads();
            scan[threadIdx.x] += v;
            __syncthreads();
        }
        int excl = scan[threadIdx.x] - pred;
        if (pred){
            int slot = base + excl;
            g_tok[slot] = t;
            g_cw [slot] = w;
        }
        int total = scan[255];
        __syncthreads();
        base += total;
    }
}

// ---------------- bf16 3-pass grouped GEMM (R5 machinery, BM=64, 2 CTA/SM) ----
// MODE 0: B tile = 64 gate + 64 up rows at n0=bx*64; epilogue silu(g)*u -> g_hhi/lo
// MODE 1: B tile = 128 out cols at n0=bx*128; epilogue atomicAdd coef*acc -> out
template<int MODE>
__global__ void __launch_bounds__(256, 2)
moe_gemm(float* __restrict__ out)
{
    const int e   = blockIdx.z;
    const int off = g_off[e];
    const int cnt = g_off[e+1] - off;
    const int m0  = blockIdx.y * BM;
    if (m0 >= cnt) return;
    const int n0  = blockIdx.x * ((MODE == 0) ? 64 : 128);

    extern __shared__ __align__(1024) char smem[];
    const uint32_t sb = smem_u32(smem);
    const int tid = threadIdx.x, wid = tid >> 5, lane = tid & 31;

    // ---- producer: thread t owns row tid>>1, half tid&1 (R5 idiom).
    // B rows 0..127 (all threads); A rows 0..63 (threads with prow<64 only).
    const int prow  = tid >> 1;
    const int phalf = tid & 1;
    const bool pa_act = (prow < BM);
    const __nv_bfloat16 *pa_hi, *pa_lo, *pb_hi, *pb_lo;
    {
        int mr = m0 + (pa_act ? prow : 0);
        bool v = (mr < cnt);
        if (MODE == 0){
            size_t ar = (size_t)(v ? g_tok[off + mr] : 0) * H_DIM;
            pa_hi = g_xhi + ar; pa_lo = g_xlo + ar;
            size_t br = (size_t)e * (2*(size_t)I_DIM)
                      + (size_t)((prow < 64) ? (n0 + prow) : (I_DIM + n0 + (prow - 64)));
            pb_hi = g_wshi + br * H_DIM; pb_lo = g_wslo + br * H_DIM;
        } else {
            size_t ar = (size_t)(off + (v ? mr : 0)) * I_DIM;
            pa_hi = g_hhi + ar; pa_lo = g_hlo + ar;
            size_t br = (size_t)e * H_DIM + (size_t)(n0 + prow);
            pb_hi = g_w2hi + br * I_DIM; pb_lo = g_w2lo + br * I_DIM;
        }
    }
    const uint32_t psw = (uint32_t)((prow & 7) * 16);
    const uint32_t d0  = (uint32_t)(prow*ROWB) + (((uint32_t)(phalf*32))      ^ psw);
    const uint32_t d1  = (uint32_t)(prow*ROWB) + (((uint32_t)(phalf*32 + 16)) ^ psw);
    const uint32_t d0l = (uint32_t)(prow*ROWB) + (((uint32_t)(64 + phalf*32))      ^ psw);
    const uint32_t d1l = (uint32_t)(prow*ROWB) + (((uint32_t)(64 + phalf*32 + 16)) ^ psw);

    #define ISSUE(c) do { \
        uint32_t stg = sb + (uint32_t)(((c) & 3) * STG_BYTES); \
        int k0 = (c)*BK + phalf*16; \
        if (pa_act){ \
            CPA(stg + d0,  pa_hi + k0);     \
            CPA(stg + d1,  pa_hi + k0 + 8); \
            CPA(stg + d0l, pa_lo + k0);     \
            CPA(stg + d1l, pa_lo + k0 + 8); \
        } \
        CPA(stg + A_BYTES + d0,  pb_hi + k0);     \
        CPA(stg + A_BYTES + d1,  pb_hi + k0 + 8); \
        CPA(stg + A_BYTES + d0l, pb_lo + k0);     \
        CPA(stg + A_BYTES + d1l, pb_lo + k0 + 8); \
    } while(0)

    // ---- consumer: warp tile 32m x 32n at (wm*32, wn*32)
    const int wm = wid & 1, wn = wid >> 1;
    const int lrow8 = (lane & 7) + ((lane >> 3) & 1) * 8;
    const int lc16  = ((lane >> 4) & 1) * 16;
    const uint32_t xorv = (uint32_t)((lane & 7) * 16);
    uint32_t aOff[2], bOff[2];
    #pragma unroll
    for (int mi = 0; mi < 2; mi++)
        aOff[mi] = (uint32_t)((wm*32 + mi*16 + lrow8) * ROWB);
    #pragma unroll
    for (int nb = 0; nb < 2; nb++)
        bOff[nb] = (uint32_t)(A_BYTES + (wn*32 + nb*16 + lrow8) * ROWB);

    float acc[2][4][4];
    #pragma unroll
    for (int mi = 0; mi < 2; mi++)
        #pragma unroll
        for (int ni = 0; ni < 4; ni++)
            #pragma unroll
            for (int q = 0; q < 4; q++) acc[mi][ni][q] = 0.0f;

    // ---- pipeline (R5 verbatim) ----
    #pragma unroll
    for (int c = 0; c < NSTAGE-1; c++){ ISSUE(c); CP_COMMIT(); }

    for (int c = 0; c < NCH; c++){
        CP_WAIT2();
        __syncthreads();
        if (c + NSTAGE-1 < NCH) ISSUE(c + NSTAGE-1);
        CP_COMMIT();

        const uint32_t stg = sb + (uint32_t)((c & 3) * STG_BYTES);
        #pragma unroll
        for (int kc = 0; kc < 2; kc++){
            const uint32_t hiB = (uint32_t)(kc*32 + lc16);
            const uint32_t loB = hiB + 64;
            uint32_t bh[2][4], bl[2][4], af[2][4];
            #pragma unroll
            for (int nb = 0; nb < 2; nb++){
                ldsm4(bh[nb], stg + bOff[nb] + (hiB ^ xorv));
                ldsm4(bl[nb], stg + bOff[nb] + (loB ^ xorv));
            }
            #pragma unroll
            for (int mi = 0; mi < 2; mi++)
                ldsm4(af[mi], stg + aOff[mi] + (hiB ^ xorv));
            #pragma unroll
            for (int mi = 0; mi < 2; mi++)
                #pragma unroll
                for (int ni = 0; ni < 4; ni++){
                    const int nb = ni >> 1, sel = ni & 1;
                    uint32_t b0h = sel ? bh[nb][1] : bh[nb][0];
                    uint32_t b1h = sel ? bh[nb][3] : bh[nb][2];
                    uint32_t b0l = sel ? bl[nb][1] : bl[nb][0];
                    uint32_t b1l = sel ? bl[nb][3] : bl[nb][2];
                    mma_bf16(acc[mi][ni], af[mi], b0h, b1h);
                    mma_bf16(acc[mi][ni], af[mi], b0l, b1l);
                }
            #pragma unroll
            for (int mi = 0; mi < 2; mi++)
                ldsm4(af[mi], stg + aOff[mi] + (loB ^ xorv));
            #pragma unroll
            for (int mi = 0; mi < 2; mi++)
                #pragma unroll
                for (int ni = 0; ni < 4; ni++){
                    const int nb = ni >> 1, sel = ni & 1;
                    uint32_t b0h = sel ? bh[nb][1] : bh[nb][0];
                    uint32_t b1h = sel ? bh[nb][3] : bh[nb][2];
                    mma_bf16(acc[mi][ni], af[mi], b0h, b1h);
                }
        }
    }

    CP_WAIT0();
    __syncthreads();

    // ---- epilogue ----
    const int row_l = lane >> 2;
    const int col2  = (lane & 3) * 2;

    if (MODE == 0){
        float* ub = (float*)smem;          // [64][66] fp32, reuses stage smem
        if (wn >= 2){                      // up warps (cols 64..127 of B tile)
            #pragma unroll
            for (int mi = 0; mi < 2; mi++)
                #pragma unroll
                for (int ni = 0; ni < 4; ni++){
                    int r  = wm*32 + mi*16 + row_l;
                    int cu = (wn - 2)*32 + ni*8 + col2;
                    ub[(r    )*66 + cu]     = acc[mi][ni][0];
                    ub[(r    )*66 + cu + 1] = acc[mi][ni][1];
                    ub[(r + 8)*66 + cu]     = acc[mi][ni][2];
                    ub[(r + 8)*66 + cu + 1] = acc[mi][ni][3];
                }
        }
        __syncthreads();
        if (wn < 2){                       // gate warps: silu(g)*u -> g_hhi/lo
            #pragma unroll
            for (int mi = 0; mi < 2; mi++)
                #pragma unroll
                for (int ni = 0; ni < 4; ni++){
                    int r  = wm*32 + mi*16 + row_l;
                    int cg = wn*32 + ni*8 + col2;
                    #pragma unroll
                    for (int half = 0; half < 2; half++){
                        int rr = r + half*8;
                        int mg = m0 + rr;
                        if (mg < cnt){
                            float g0 = acc[mi][ni][half*2], g1 = acc[mi][ni][half*2+1];
                            float u0 = ub[rr*66 + cg], u1 = ub[rr*66 + cg + 1];
                            float h0 = g0 / (1.0f + __expf(-g0)) * u0;
                            float h1 = g1 / (1.0f + __expf(-g1)) * u1;
                            uint32_t hi, lo;
                            split2(h0, h1, hi, lo);
                            size_t idx = (size_t)(off + mg) * I_DIM + n0 + cg;
                            *(uint32_t*)(g_hhi + idx) = hi;
                            *(uint32_t*)(g_hlo + idx) = lo;
                        }
                    }
                }
        }
    } else {
        // coef-scaled accumulate: exactly two commutative atomic adds per out
        // element onto a zeroed location -> bitwise deterministic.
        #pragma unroll
        for (int mi = 0; mi < 2; mi++)
            #pragma unroll
            for (int ni = 0; ni < 4; ni++){
                int r  = wm*32 + mi*16 + row_l;
                int cc = n0 + wn*32 + ni*8 + col2;
                #pragma unroll
                for (int half = 0; half < 2; half++){
                    int rr = r + half*8;
                    int mg = m0 + rr;
                    if (mg < cnt){
                        float w = g_cw[off + mg];
                        float* dst = out + (size_t)g_tok[off + mg] * H_DIM + cc;
                        atomicAdd(dst,     w * acc[mi][ni][half*2]);
                        atomicAdd(dst + 1, w * acc[mi][ni][half*2+1]);
                    }
                }
            }
    }
    #undef ISSUE
}

// ---------------- launch ----------------
extern "C" void kernel_launch(void* const* d_in, const int* in_sizes, int n_in,
                              void* d_out, int out_size)
{
    const float* x      = (const float*)d_in[0];   // [T, H]
    const float* gate_w = (const float*)d_in[1];   // [E, H]
    const float* ws     = (const float*)d_in[2];   // [E, 2I, H]
    const float* w2s    = (const float*)d_in[3];   // [E, H, I]
    float* out = (float*)d_out;                    // [T, H]

    cudaFuncSetAttribute(moe_gemm<0>, cudaFuncAttributeMaxDynamicSharedMemorySize, SMEM_DYN);
    cudaFuncSetAttribute(moe_gemm<1>, cudaFuncAttributeMaxDynamicSharedMemorySize, SMEM_DYN);

    const int n4x  = T_TOK * H_DIM / 4;
    const int n4ws = N_EXP * 2 * I_DIM * (H_DIM / 4);
    const int n4w2 = N_EXP * H_DIM * (I_DIM / 4);

    zero_kernel <<<(T_TOK*H_DIM/4)/256, 256>>>((float4*)out);
    split_kernel<1><<<n4ws / 256, 256>>>((const float4*)ws,  n4ws);
    split_kernel<2><<<n4w2 / 256, 256>>>((const float4*)w2s, n4w2);
    split_kernel<0><<<n4x  / 256, 256>>>((const float4*)x,   n4x);
    gate_kernel <<<T_TOK, 128>>>(x, gate_w);
    group_kernel<<<N_EXP, 256>>>();

    moe_gemm<0> <<<dim3(I_DIM/64,  T_TOK/BM, N_EXP), 256, SMEM_DYN>>>(out);
    moe_gemm<1> <<<dim3(H_DIM/128, T_TOK/BM, N_EXP), 256, SMEM_DYN>>>(out);
}